// round 2
// baseline (speedup 1.0000x reference)
#include <cuda_runtime.h>
#include <stdint.h>

// UndoMaxPooling2D: out = zeros(N_OUT); out[pos[i]] = x[i], last-index-wins
// (matches XLA sequential scatter-set semantics for duplicate indices).
//
// Strategy: reuse d_out as an int winner-index buffer.
//   1. memset out to 0xFF (int -1 everywhere)               [graph-capturable]
//   2. atomicMax((int*)out)[pos[i]] = i  (unique i => last-index-wins)
//   3. in-place: out[o] = (w = winner[o]) >= 0 ? x[w] : 0.0f
// out (103MB) stays resident in L2 (126MB) across all three passes, so only
// the final float contents write back to DRAM.
//
// Shapes fixed by the problem:
#define N_IN   (32 * 56 * 56 * 64)     // 6,422,528   (divisible by 4)
#define N_OUT  (32 * 112 * 112 * 64)   // 25,690,112  (divisible by 4)

// ---------------------------------------------------------------------------
// Kernel 1: atomicMax of source index into winner[pos[i]].
// ---------------------------------------------------------------------------
__global__ void __launch_bounds__(256) scatter_winner_kernel(const int* __restrict__ pos,
                                                             int* __restrict__ winner) {
    int idx = blockIdx.x * blockDim.x + threadIdx.x;   // N_IN/4 threads
    if (idx < N_IN / 4) {
        int4 p = reinterpret_cast<const int4*>(pos)[idx];
        int base = idx * 4;
        atomicMax(&winner[p.x], base + 0);
        atomicMax(&winner[p.y], base + 1);
        atomicMax(&winner[p.z], base + 2);
        atomicMax(&winner[p.w], base + 3);
    }
}

// ---------------------------------------------------------------------------
// Kernel 2: in-place winner-index -> value transform.
// Reads int4 winner indices from out, writes float4 values to the same slots.
// Each thread owns its 4 slots exclusively, so the in-place RMW is race-free.
// x gathers are random but x (26MB) is L2-resident with ~8x sector reuse.
// ---------------------------------------------------------------------------
__global__ void __launch_bounds__(256) resolve_out_kernel(const float* __restrict__ x,
                                                          float* __restrict__ out) {
    int idx = blockIdx.x * blockDim.x + threadIdx.x;   // N_OUT/4 threads
    if (idx < N_OUT / 4) {
        int4 w = reinterpret_cast<const int4*>(out)[idx];
        float4 o;
        o.x = (w.x >= 0) ? __ldg(&x[w.x]) : 0.0f;
        o.y = (w.y >= 0) ? __ldg(&x[w.y]) : 0.0f;
        o.z = (w.z >= 0) ? __ldg(&x[w.z]) : 0.0f;
        o.w = (w.w >= 0) ? __ldg(&x[w.w]) : 0.0f;
        reinterpret_cast<float4*>(out)[idx] = o;
    }
}

// ---------------------------------------------------------------------------
// Launch: memset + two dependent kernels on the capture stream (stream 0).
// Graph-capturable: async memset + kernel launches only, no allocs, no syncs.
// ---------------------------------------------------------------------------
extern "C" void kernel_launch(void* const* d_in, const int* in_sizes, int n_in,
                              void* d_out, int out_size) {
    const float* x   = (const float*)d_in[0];
    const int*   pos = (const int*)d_in[1];
    float*       out = (float*)d_out;

    const int threads = 256;
    const int grid_scatter = (N_IN  / 4 + threads - 1) / threads;  // 6272
    const int grid_resolve = (N_OUT / 4 + threads - 1) / threads;  // 25088

    // out := -1 (all bytes 0xFF) — winner sentinel
    cudaMemsetAsync(d_out, 0xFF, (size_t)N_OUT * sizeof(int), 0);
    scatter_winner_kernel<<<grid_scatter, threads>>>(pos, (int*)out);
    resolve_out_kernel<<<grid_resolve, threads>>>(x, out);
}

// round 5
// speedup vs baseline: 1.4110x; 1.4110x over previous
#include <cuda_runtime.h>
#include <stdint.h>

// UndoMaxPooling2D: out = zeros(N_OUT); out[pos[i]] = x[i], last-index-wins
// (matches XLA sequential scatter-set: max source index wins, indices unique).
//
// Strategy: reuse d_out as int winner buffer, processed in TWO HALVES so each
// half's winner region (51.5MB) stays L2-resident (126MB L2) across
// memset -> atomic scatter -> in-place resolve. Atomics become L2-hit RMWs
// instead of DRAM sector ping-pong; only final floats write back to DRAM.
// pos is read with __ldcs (evict-first), final out stores use __stcs so the
// dead half-1 output doesn't crowd half-2's working set out of L2.
//
// Shapes fixed by the problem:
#define N_IN   (32 * 56 * 56 * 64)     // 6,422,528   (div by 1024)
#define N_OUT  (32 * 112 * 112 * 64)   // 25,690,112  (div by 2048)
#define HALF   (N_OUT / 2)             // 12,845,056

// ---------------------------------------------------------------------------
// Scatter: atomicMax of source index into winner[pos[i]], only for positions
// inside [lo, hi). Return value unused -> RED.E.MAX (fire-and-forget).
// ---------------------------------------------------------------------------
__global__ void __launch_bounds__(256) scatter_half_kernel(const int* __restrict__ pos,
                                                           int* __restrict__ winner,
                                                           int lo, int hi) {
    int idx = blockIdx.x * blockDim.x + threadIdx.x;   // N_IN/4 threads
    if (idx < N_IN / 4) {
        int4 p = __ldcs(reinterpret_cast<const int4*>(pos) + idx);  // streaming read
        int base = idx * 4;
        if (p.x >= lo && p.x < hi) atomicMax(&winner[p.x], base + 0);
        if (p.y >= lo && p.y < hi) atomicMax(&winner[p.y], base + 1);
        if (p.z >= lo && p.z < hi) atomicMax(&winner[p.z], base + 2);
        if (p.w >= lo && p.w < hi) atomicMax(&winner[p.w], base + 3);
    }
}

// ---------------------------------------------------------------------------
// Resolve: in-place winner-index -> value transform on one half.
// Reads int4 winners from out (L2-hot), gathers x (26MB, ~8x sector reuse,
// L2-resident), writes float4 back to the same lines with evict-first hint
// (data is final; don't let it crowd the next half's working set).
// Each thread owns its 4 slots exclusively -> race-free in-place RMW.
// ---------------------------------------------------------------------------
__global__ void __launch_bounds__(256) resolve_half_kernel(const float* __restrict__ x,
                                                           float* __restrict__ out,
                                                           int off4) {
    int idx = blockIdx.x * blockDim.x + threadIdx.x;   // HALF/4 threads
    if (idx < HALF / 4) {
        int j = off4 + idx;
        int4 w = reinterpret_cast<const int4*>(out)[j];
        float4 o;
        o.x = (w.x >= 0) ? __ldg(&x[w.x]) : 0.0f;
        o.y = (w.y >= 0) ? __ldg(&x[w.y]) : 0.0f;
        o.z = (w.z >= 0) ? __ldg(&x[w.z]) : 0.0f;
        o.w = (w.w >= 0) ? __ldg(&x[w.w]) : 0.0f;
        __stcs(reinterpret_cast<float4*>(out) + j, o);   // evict-first final store
    }
}

// ---------------------------------------------------------------------------
// Launch: per half -> memset(0xFF sentinel) -> scatter -> resolve.
// All on the capture stream; graph-capturable (async memset + launches only).
// ---------------------------------------------------------------------------
extern "C" void kernel_launch(void* const* d_in, const int* in_sizes, int n_in,
                              void* d_out, int out_size) {
    const float* x   = (const float*)d_in[0];
    const int*   pos = (const int*)d_in[1];
    float*       out = (float*)d_out;
    int*         w   = (int*)d_out;

    const int threads = 256;
    const int grid_scatter = (N_IN / 4) / threads;   // 6272 (exact)
    const int grid_resolve = (HALF / 4) / threads;   // 12544 (exact)

    // ---- Half 1: outputs [0, HALF) ----
    cudaMemsetAsync(w, 0xFF, (size_t)HALF * sizeof(int), 0);
    scatter_half_kernel<<<grid_scatter, threads>>>(pos, w, 0, HALF);
    resolve_half_kernel<<<grid_resolve, threads>>>(x, out, 0);

    // ---- Half 2: outputs [HALF, N_OUT) ----
    cudaMemsetAsync(w + HALF, 0xFF, (size_t)HALF * sizeof(int), 0);
    scatter_half_kernel<<<grid_scatter, threads>>>(pos, w, HALF, N_OUT);
    resolve_half_kernel<<<grid_resolve, threads>>>(x, out, HALF / 4);
}